// round 1
// baseline (speedup 1.0000x reference)
#include <cuda_runtime.h>
#include <math.h>

#define TT 4096
#define EE 512
#define HH 512

// ---------------- scratch (static device globals; no allocation) ----------------
__device__ float g_e[TT];
__device__ float g_xpf[(size_t)TT * 1536];
__device__ float g_xpb[(size_t)TT * 1536];
__device__ float g_out[(size_t)TT * 1024];     // [t][2H]  (fwd 0..511, bwd 512..1023)
__device__ unsigned long long g_hbuf[2][2][HH]; // [dir][parity][j]: hi=tag(step), lo=float bits
__device__ float g_hid[1024];
__device__ float g_logits[TT];

// ---------------- helpers ----------------
__device__ __forceinline__ unsigned long long ldrelax(const unsigned long long* p) {
    unsigned long long v;
    asm volatile("ld.relaxed.gpu.global.u64 %0, [%1];" : "=l"(v) : "l"(p));
    return v;
}
__device__ __forceinline__ void strelax(unsigned long long* p, unsigned long long v) {
    asm volatile("st.relaxed.gpu.global.u64 [%0], %1;" :: "l"(p), "l"(v));
}

// ---------------- init tagged h buffers ----------------
__global__ void k_init() {
    int i = threadIdx.x; // 512 threads
    for (int d = 0; d < 2; d++) {
        g_hbuf[d][0][i] = 0ull;                     // tag 0, h=0.0f  (state before step 0)
        g_hbuf[d][1][i] = 0xFFFFFFFF00000000ull;    // invalid tag
    }
}

// ---------------- e[t] = dot(query[t], fc_w) + fc_b ----------------
__global__ void k_e(const float* __restrict__ q, const float* __restrict__ fcw,
                    const float* __restrict__ fcb) {
    int t = blockIdx.x * 8 + (threadIdx.x >> 5);
    int l = threadIdx.x & 31;
    const float* row = q + (size_t)t * EE;
    float s = 0.f;
    #pragma unroll
    for (int i = 0; i < 16; i++) s += row[l + 32 * i] * fcw[l + 32 * i];
    #pragma unroll
    for (int o = 16; o; o >>= 1) s += __shfl_down_sync(0xffffffffu, s, o);
    if (l == 0) g_e[t] = s + fcb[0];
}

// ---------------- energy: zero fill then diagonal ----------------
__global__ void k_zero(float* __restrict__ out, int n4) {
    float4 z = make_float4(0.f, 0.f, 0.f, 0.f);
    float4* p = (float4*)(out + 1024);
    int stride = gridDim.x * blockDim.x;
    for (int i = blockIdx.x * blockDim.x + threadIdx.x; i < n4; i += stride) p[i] = z;
}
__global__ void k_diag(float* __restrict__ out) {
    int i = blockIdx.x * blockDim.x + threadIdx.x;
    if (i < TT) out[1024 + (size_t)i * (TT + 1)] = g_e[i];
}

// ---------------- GEMM: Co[t][n] = sum_k (e[t]*A[t][k]) * W[n][k] + bias[n] ----------------
// BM=128, BN=64, BK=16, 256 threads, thread tile 8x4
__global__ void __launch_bounds__(256) k_gemm(const float* __restrict__ A,
                                              const float* __restrict__ W,
                                              const float* __restrict__ bias,
                                              int which) {
    float* __restrict__ Co = which ? g_xpb : g_xpf;
    __shared__ float As[16][128];
    __shared__ float Bs[16][64];
    int tid = threadIdx.x;
    int tx = tid & 15, ty = tid >> 4;
    int m0 = blockIdx.y * 128, n0 = blockIdx.x * 64;

    int aRow = tid >> 2;          // 0..63
    int aCol = (tid & 3) * 4;     // 0,4,8,12
    float e0 = g_e[m0 + aRow];
    float e1 = g_e[m0 + aRow + 64];

    float acc[8][4];
    #pragma unroll
    for (int i = 0; i < 8; i++)
        #pragma unroll
        for (int j = 0; j < 4; j++) acc[i][j] = 0.f;

    for (int k0 = 0; k0 < EE; k0 += 16) {
        float4 a0 = *(const float4*)(A + (size_t)(m0 + aRow) * EE + k0 + aCol);
        float4 a1 = *(const float4*)(A + (size_t)(m0 + aRow + 64) * EE + k0 + aCol);
        float4 b0 = *(const float4*)(W + (size_t)(n0 + aRow) * EE + k0 + aCol);
        __syncthreads();
        As[aCol + 0][aRow] = a0.x * e0; As[aCol + 1][aRow] = a0.y * e0;
        As[aCol + 2][aRow] = a0.z * e0; As[aCol + 3][aRow] = a0.w * e0;
        As[aCol + 0][aRow + 64] = a1.x * e1; As[aCol + 1][aRow + 64] = a1.y * e1;
        As[aCol + 2][aRow + 64] = a1.z * e1; As[aCol + 3][aRow + 64] = a1.w * e1;
        Bs[aCol + 0][aRow] = b0.x; Bs[aCol + 1][aRow] = b0.y;
        Bs[aCol + 2][aRow] = b0.z; Bs[aCol + 3][aRow] = b0.w;
        __syncthreads();
        #pragma unroll
        for (int kk = 0; kk < 16; kk++) {
            float4 av0 = *(float4*)&As[kk][ty * 8];
            float4 av1 = *(float4*)&As[kk][ty * 8 + 4];
            float4 bv  = *(float4*)&Bs[kk][tx * 4];
            float av[8] = {av0.x, av0.y, av0.z, av0.w, av1.x, av1.y, av1.z, av1.w};
            float bb[4] = {bv.x, bv.y, bv.z, bv.w};
            #pragma unroll
            for (int i = 0; i < 8; i++)
                #pragma unroll
                for (int j = 0; j < 4; j++) acc[i][j] += av[i] * bb[j];
        }
    }
    float bb0 = bias[n0 + tx * 4 + 0], bb1 = bias[n0 + tx * 4 + 1];
    float bb2 = bias[n0 + tx * 4 + 2], bb3 = bias[n0 + tx * 4 + 3];
    #pragma unroll
    for (int i = 0; i < 8; i++) {
        int m = m0 + ty * 8 + i;
        float4 v = make_float4(acc[i][0] + bb0, acc[i][1] + bb1,
                               acc[i][2] + bb2, acc[i][3] + bb3);
        *(float4*)(Co + (size_t)m * 1536 + n0 + tx * 4) = v;
    }
}

// ---------------- persistent bidirectional GRU ----------------
// grid = 128 CTAs (64 per direction), 256 threads. CTA owns 8 h-indices; warp w owns index jbase+w.
// Weights (3 rows of 512) live in registers: 48 regs/thread.
__global__ void __launch_bounds__(256) k_gru(const float* __restrict__ whhf,
                                             const float* __restrict__ bhhf,
                                             const float* __restrict__ whhb,
                                             const float* __restrict__ bhhb) {
    int dir = blockIdx.x >> 6;
    int cb  = blockIdx.x & 63;
    const float* whh = dir ? whhb : whhf;
    const float* bhh = dir ? bhhb : bhhf;
    const float* xp  = dir ? g_xpb : g_xpf;
    int tid = threadIdx.x, w = tid >> 5, l = tid & 31;
    int j = cb * 8 + w;

    float wr[3][16];
    #pragma unroll
    for (int g = 0; g < 3; g++) {
        const float* row = whh + (size_t)(g * 512 + j) * 512;
        #pragma unroll
        for (int c = 0; c < 4; c++) {
            float4 v = *(const float4*)(row + c * 128 + l * 4);
            wr[g][c * 4 + 0] = v.x; wr[g][c * 4 + 1] = v.y;
            wr[g][c * 4 + 2] = v.z; wr[g][c * 4 + 3] = v.w;
        }
    }
    float bh0 = bhh[j], bh1 = bhh[512 + j], bh2 = bhh[1024 + j];
    float hold = 0.f;
    __shared__ float hs[512];
    unsigned long long* bufA = g_hbuf[dir][0];
    unsigned long long* bufB = g_hbuf[dir][1];

    for (int t = 0; t < TT; t++) {
        // prefetch xp row early (hidden under poll)
        const float* xprow = xp + (size_t)(dir ? (TT - 1 - t) : t) * 1536;
        float xr = 0.f, xz = 0.f, xn = 0.f;
        if (l == 0) { xr = __ldg(xprow + j); xz = __ldg(xprow + 512 + j); xn = __ldg(xprow + 1024 + j); }

        unsigned long long* src = (t & 1) ? bufB : bufA;
        unsigned tg = (unsigned)t;
        unsigned long long v0 = ldrelax(src + tid);
        while ((unsigned)(v0 >> 32) != tg) v0 = ldrelax(src + tid);
        unsigned long long v1 = ldrelax(src + tid + 256);
        while ((unsigned)(v1 >> 32) != tg) v1 = ldrelax(src + tid + 256);
        hs[tid]       = __uint_as_float((unsigned)v0);
        hs[tid + 256] = __uint_as_float((unsigned)v1);
        __syncthreads();

        float a0 = 0.f, a1 = 0.f, a2 = 0.f;
        #pragma unroll
        for (int c = 0; c < 4; c++) {
            float4 hv = *(const float4*)&hs[c * 128 + l * 4];
            a0 += wr[0][c*4+0]*hv.x + wr[0][c*4+1]*hv.y + wr[0][c*4+2]*hv.z + wr[0][c*4+3]*hv.w;
            a1 += wr[1][c*4+0]*hv.x + wr[1][c*4+1]*hv.y + wr[1][c*4+2]*hv.z + wr[1][c*4+3]*hv.w;
            a2 += wr[2][c*4+0]*hv.x + wr[2][c*4+1]*hv.y + wr[2][c*4+2]*hv.z + wr[2][c*4+3]*hv.w;
        }
        #pragma unroll
        for (int o = 16; o; o >>= 1) {
            a0 += __shfl_down_sync(0xffffffffu, a0, o);
            a1 += __shfl_down_sync(0xffffffffu, a1, o);
            a2 += __shfl_down_sync(0xffffffffu, a2, o);
        }
        if (l == 0) {
            float r = 1.f / (1.f + expf(-(xr + a0 + bh0)));
            float z = 1.f / (1.f + expf(-(xz + a1 + bh1)));
            float n = tanhf(xn + r * (a2 + bh2));
            float hnew = (1.f - z) * n + z * hold;
            hold = hnew;
            int orow = dir ? (TT - 1 - t) : t;
            g_out[(size_t)orow * 1024 + dir * 512 + j] = hnew;
            unsigned long long pv = ((unsigned long long)(unsigned)(t + 1) << 32) |
                                    (unsigned long long)__float_as_uint(hnew);
            strelax(((t & 1) ? bufA : bufB) + j, pv);
        }
        // No trailing barrier needed: a thread only overwrites hs after its poll sees tag t+1,
        // which requires every warp's lane0 store (data-dependent on that warp's hs reads).
    }
}

// ---------------- attention epilogue ----------------
__global__ void k_hid() {
    int i = blockIdx.x * blockDim.x + threadIdx.x;
    if (i < 512) g_hid[i] = g_out[512 + i];                                // hb_last
    else if (i < 1024) g_hid[i] = g_out[(size_t)4095 * 1024 + (i - 512)];  // hf_last
}

__global__ void k_logits() {
    int t = blockIdx.x * 8 + (threadIdx.x >> 5);
    int l = threadIdx.x & 31;
    const float* row = g_out + (size_t)t * 1024;
    float s = 0.f;
    #pragma unroll
    for (int i = 0; i < 32; i++) s += row[l + 32 * i] * g_hid[l + 32 * i];
    #pragma unroll
    for (int o = 16; o; o >>= 1) s += __shfl_down_sync(0xffffffffu, s, o);
    if (l == 0) g_logits[t] = s * 0.03125f;  // 1/sqrt(1024)
}

__global__ void k_softmax() {
    __shared__ float red1[32], red2[32];
    int tid = threadIdx.x;
    float m = -1e30f;
    for (int i = tid; i < TT; i += 1024) m = fmaxf(m, g_logits[i]);
    #pragma unroll
    for (int o = 16; o; o >>= 1) m = fmaxf(m, __shfl_xor_sync(0xffffffffu, m, o));
    if ((tid & 31) == 0) red1[tid >> 5] = m;
    __syncthreads();
    if (tid < 32) {
        float v = red1[tid];
        #pragma unroll
        for (int o = 16; o; o >>= 1) v = fmaxf(v, __shfl_xor_sync(0xffffffffu, v, o));
        if (tid == 0) red1[0] = v;
    }
    __syncthreads();
    m = red1[0];
    float s = 0.f;
    for (int i = tid; i < TT; i += 1024) s += expf(g_logits[i] - m);
    #pragma unroll
    for (int o = 16; o; o >>= 1) s += __shfl_xor_sync(0xffffffffu, s, o);
    if ((tid & 31) == 0) red2[tid >> 5] = s;
    __syncthreads();
    if (tid < 32) {
        float v = red2[tid];
        #pragma unroll
        for (int o = 16; o; o >>= 1) v += __shfl_xor_sync(0xffffffffu, v, o);
        if (tid == 0) red2[0] = v;
    }
    __syncthreads();
    float inv = 1.f / red2[0];
    for (int i = tid; i < TT; i += 1024) g_logits[i] = expf(g_logits[i] - m) * inv;
}

__global__ void k_lin(float* __restrict__ out) {
    // 16 CTAs x 256 threads; CTA c handles columns [c*64, c*64+64)
    int c = blockIdx.x;
    int jj = threadIdx.x & 63;
    int rr = threadIdx.x >> 6;  // 0..3
    int col = c * 64 + jj;
    float acc = 0.f;
    for (int t = rr; t < TT; t += 4) acc += g_logits[t] * g_out[(size_t)t * 1024 + col];
    __shared__ float sm[4][64];
    sm[rr][jj] = acc;
    __syncthreads();
    if (rr == 0) out[col] = sm[0][jj] + sm[1][jj] + sm[2][jj] + sm[3][jj];
}

// ---------------- launch ----------------
extern "C" void kernel_launch(void* const* d_in, const int* in_sizes, int n_in,
                              void* d_out, int out_size) {
    const float* input = (const float*)d_in[0];
    const float* query = (const float*)d_in[1];
    const float* fc_w  = (const float*)d_in[2];
    const float* fc_b  = (const float*)d_in[3];
    const float* wihf  = (const float*)d_in[4];
    const float* whhf  = (const float*)d_in[5];
    const float* bihf  = (const float*)d_in[6];
    const float* bhhf  = (const float*)d_in[7];
    const float* wihb  = (const float*)d_in[8];
    const float* whhb  = (const float*)d_in[9];
    const float* bihb  = (const float*)d_in[10];
    const float* bhhb  = (const float*)d_in[11];
    float* out = (float*)d_out;

    int n4 = (out_size - 1024) / 4;  // energy float4 count

    k_init<<<1, 512>>>();
    k_e<<<TT / 8, 256>>>(query, fc_w, fc_b);
    k_zero<<<4096, 256>>>(out, n4);
    k_diag<<<16, 256>>>(out);
    dim3 gg(1536 / 64, TT / 128);
    k_gemm<<<gg, 256>>>(input, wihf, bihf, 0);
    k_gemm<<<gg, 256>>>(input, wihb, bihb, 1);
    k_gru<<<128, 256>>>(whhf, bhhf, whhb, bhhb);
    k_hid<<<4, 256>>>();
    k_logits<<<TT / 8, 256>>>();
    k_softmax<<<1, 1024>>>();
    k_lin<<<16, 256>>>(out);
}